// round 17
// baseline (speedup 1.0000x reference)
#include <cuda_runtime.h>
#include <cuda_bf16.h>
#include <math.h>
#include <stdint.h>

// Problem constants
constexpr int B_ = 2, S_ = 1024, D_ = 1024, N_ = 16, H_ = 64;
constexpr int DW = D_ / 2;            // packed bf16x2 words per row
constexpr float NORM_ = 0.125f;
constexpr float BIGC_ = 1000000.0f;
constexpr float LNEPS_ = 1e-5f;

// Scratch (static device globals — no runtime allocation)
__device__ __align__(16) uint32_t g_qhw[B_ * S_ * DW];   // qh packed bf16x2 (h pairs)
__device__ __align__(16) uint32_t g_khw[B_ * S_ * DW];   // kh -> KS packed
__device__ __align__(16) uint32_t g_vhw[B_ * S_ * DW];   // vh packed (h pairs)
__device__ __align__(16) uint32_t g_rp [S_ * DW];        // r packed
__device__ __align__(16) float    g_rw [D_ * D_];        // r_kernel transposed [D, N*H]
__device__ __align__(16) float    g_cvec[B_ * N_ * S_];
__device__ __align__(16) uint32_t g_ow [B_ * S_ * DW];   // attn out packed

// ---------------------------------------------------------------------------
// bf16 helpers
// ---------------------------------------------------------------------------
__device__ __forceinline__ uint32_t pk(float a, float b) {
    __nv_bfloat162 t = __floats2bfloat162_rn(a, b);
    return *reinterpret_cast<uint32_t*>(&t);
}
__device__ __forceinline__ float2 upk(uint32_t w) {
    __nv_bfloat162 t = *reinterpret_cast<__nv_bfloat162*>(&w);
    return __bfloat1622float2(t);
}
__device__ __forceinline__ void mma16(float* c, const uint32_t* a, const uint32_t* b) {
    asm volatile(
        "mma.sync.aligned.m16n8k16.row.col.f32.bf16.bf16.f32 "
        "{%0,%1,%2,%3},{%4,%5,%6,%7},{%8,%9},{%0,%1,%2,%3};\n"
        : "+f"(c[0]), "+f"(c[1]), "+f"(c[2]), "+f"(c[3])
        : "r"(a[0]), "r"(a[1]), "r"(a[2]), "r"(a[3]), "r"(b[0]), "r"(b[1]));
}

// ---------------------------------------------------------------------------
// r_kernel transpose: [N, D, H] -> g_rw [D, N*H] (fp32).
// ---------------------------------------------------------------------------
__global__ void rk_transpose(const float* __restrict__ rk)
{
    const int idx = blockIdx.x * blockDim.x + threadIdx.x;   // 0 .. 16383
    const int d = idx >> 4, n = idx & 15;
    const float4* src = reinterpret_cast<const float4*>(
        rk + ((long long)n * D_ + d) * H_);
    float4* dst = reinterpret_cast<float4*>(g_rw + (long long)d * D_ + n * H_);
#pragma unroll
    for (int i = 0; i < 16; i++) dst[i] = src[i];
}

// ---------------------------------------------------------------------------
// Multi-batch NN bf16 GEMM (q/k/v/r projections in one launch).
// All outputs packed bf16x2 words.
// ---------------------------------------------------------------------------
struct GemmBatch {
    const float* A;
    const float* Bm;
    const float* bias;
    uint32_t*    C;
    int          M;
};
struct GemmBatch4 { GemmBatch b[4]; };

template <int BM, int BN, int WMS, int WNS>
__global__ void __launch_bounds__(WMS * WNS * 32)
tgemm_multi(GemmBatch4 bs, int K, int lda, int ldb)
{
    constexpr int NTHR = WMS * WNS * 32;
    constexpr int BKW  = 12;            // 8 words (k16) + pad 4
    constexpr int WTM  = BM / WMS, WTN = BN / WNS;
    constexpr int MT   = WTM / 16, NT2 = WTN / 8;
    constexpr int AV   = 4 * BM / NTHR;
    constexpr int BV   = 4 * BN / NTHR;

    const GemmBatch P = bs.b[blockIdx.z];
    const int m0 = blockIdx.y * BM, n0 = blockIdx.x * BN;
    if (m0 >= P.M) return;

    __shared__ uint32_t As[2][BM][BKW];
    __shared__ uint32_t Bs[2][BN][BKW];

    const float* A  = P.A;
    const float* Bm = P.Bm;

    const int tid = threadIdx.x, lane = tid & 31, wid = tid >> 5;
    const int g = lane >> 2, tig = lane & 3;
    const int wm = wid / WNS, wn = wid % WNS;

    float4 aSt[AV];
    float  bSt[BV][4];
    const int NK = K / 16;

    auto loadG = [&](int k0) {
#pragma unroll
        for (int i = 0; i < AV; i++) {
            int v = tid + i * NTHR; int row = v >> 2, c4 = v & 3;
            aSt[i] = *reinterpret_cast<const float4*>(
                A + (long long)(m0 + row) * lda + k0 + 4 * c4);
        }
#pragma unroll
        for (int i = 0; i < BV; i++) {
            int n = tid % BN; int kb = tid / BN + i * (NTHR / BN);
#pragma unroll
            for (int j = 0; j < 4; j++)
                bSt[i][j] = Bm[(long long)(k0 + kb * 4 + j) * ldb + n0 + n];
        }
    };

    auto storeS = [&](int st) {
#pragma unroll
        for (int i = 0; i < AV; i++) {
            int v = tid + i * NTHR; int row = v >> 2, c4 = v & 3;
            As[st][row][2 * c4    ] = pk(aSt[i].x, aSt[i].y);
            As[st][row][2 * c4 + 1] = pk(aSt[i].z, aSt[i].w);
        }
#pragma unroll
        for (int i = 0; i < BV; i++) {
            int n = tid % BN; int kb = tid / BN + i * (NTHR / BN);
            Bs[st][n][2 * kb    ] = pk(bSt[i][0], bSt[i][1]);
            Bs[st][n][2 * kb + 1] = pk(bSt[i][2], bSt[i][3]);
        }
    };

    float acc[MT][NT2][4];
#pragma unroll
    for (int mt = 0; mt < MT; mt++)
#pragma unroll
        for (int nt = 0; nt < NT2; nt++)
#pragma unroll
            for (int j = 0; j < 4; j++) acc[mt][nt][j] = 0.f;

    auto comp = [&](int st) {
        uint32_t af[MT][4], bf[NT2][2];
#pragma unroll
        for (int mt = 0; mt < MT; mt++) {
            int r0 = wm * WTM + mt * 16 + g;
            af[mt][0] = As[st][r0    ][tig];
            af[mt][1] = As[st][r0 + 8][tig];
            af[mt][2] = As[st][r0    ][tig + 4];
            af[mt][3] = As[st][r0 + 8][tig + 4];
        }
#pragma unroll
        for (int nt = 0; nt < NT2; nt++) {
            int c0 = wn * WTN + nt * 8 + g;
            bf[nt][0] = Bs[st][c0][tig];
            bf[nt][1] = Bs[st][c0][tig + 4];
        }
#pragma unroll
        for (int mt = 0; mt < MT; mt++)
#pragma unroll
            for (int nt = 0; nt < NT2; nt++)
                mma16(acc[mt][nt], af[mt], bf[nt]);
    };

    loadG(0); storeS(0); __syncthreads();
    int cur = 0;
    for (int it = 1; it <= NK; it++) {
        if (it < NK) loadG(it * 16);
        comp(cur);
        if (it < NK) storeS(cur ^ 1);
        __syncthreads();
        cur ^= 1;
    }

#pragma unroll
    for (int mt = 0; mt < MT; mt++) {
        int r0 = m0 + wm * WTM + mt * 16 + g;
#pragma unroll
        for (int nt = 0; nt < NT2; nt++) {
            int col = n0 + wn * WTN + nt * 8 + 2 * tig;
            float v0 = acc[mt][nt][0], v1 = acc[mt][nt][1];
            float v2 = acc[mt][nt][2], v3 = acc[mt][nt][3];
            if (P.bias) {
                float b0f = P.bias[col], b1f = P.bias[col + 1];
                v0 += b0f; v1 += b1f; v2 += b0f; v3 += b1f;
            }
            P.C[(long long)r0 * DW + (col >> 1)]       = pk(v0, v1);
            P.C[(long long)(r0 + 8) * DW + (col >> 1)] = pk(v2, v3);
        }
    }
}

// ---------------------------------------------------------------------------
// Post GEMM: A packed bf16x2 [M, DW], B fp32 [K,N]; out fp32 + bias + resid.
// ---------------------------------------------------------------------------
template <int BM, int BN, int WMS, int WNS>
__global__ void __launch_bounds__(WMS * WNS * 32)
tgemm_post(const uint32_t* __restrict__ Aw, const float* __restrict__ Bm,
           float* __restrict__ C, int K, int ldb,
           const float* __restrict__ colBias,
           const float* __restrict__ resid)
{
    constexpr int NTHR = WMS * WNS * 32;
    constexpr int BKW  = 12;
    constexpr int WTM  = BM / WMS, WTN = BN / WNS;
    constexpr int MT   = WTM / 16, NT2 = WTN / 8;
    constexpr int AV   = 4 * BM / NTHR;
    constexpr int BV   = 4 * BN / NTHR;

    __shared__ uint32_t As[2][BM][BKW];
    __shared__ uint32_t Bs[2][BN][BKW];

    const int m0 = blockIdx.y * BM, n0 = blockIdx.x * BN;
    const int tid = threadIdx.x, lane = tid & 31, wid = tid >> 5;
    const int g = lane >> 2, tig = lane & 3;
    const int wm = wid / WNS, wn = wid % WNS;

    uint2 aSt[AV];
    float bSt[BV][4];
    const int NK = K / 16;

    auto loadG = [&](int k0) {
#pragma unroll
        for (int i = 0; i < AV; i++) {
            int v = tid + i * NTHR; int row = v >> 2, c4 = v & 3;
            aSt[i] = *reinterpret_cast<const uint2*>(
                Aw + (long long)(m0 + row) * DW + (k0 >> 1) + 2 * c4);
        }
#pragma unroll
        for (int i = 0; i < BV; i++) {
            int n = tid % BN; int kb = tid / BN + i * (NTHR / BN);
#pragma unroll
            for (int j = 0; j < 4; j++)
                bSt[i][j] = Bm[(long long)(k0 + kb * 4 + j) * ldb + n0 + n];
        }
    };

    auto storeS = [&](int st) {
#pragma unroll
        for (int i = 0; i < AV; i++) {
            int v = tid + i * NTHR; int row = v >> 2, c4 = v & 3;
            As[st][row][2 * c4    ] = aSt[i].x;
            As[st][row][2 * c4 + 1] = aSt[i].y;
        }
#pragma unroll
        for (int i = 0; i < BV; i++) {
            int n = tid % BN; int kb = tid / BN + i * (NTHR / BN);
            Bs[st][n][2 * kb    ] = pk(bSt[i][0], bSt[i][1]);
            Bs[st][n][2 * kb + 1] = pk(bSt[i][2], bSt[i][3]);
        }
    };

    float acc[MT][NT2][4];
#pragma unroll
    for (int mt = 0; mt < MT; mt++)
#pragma unroll
        for (int nt = 0; nt < NT2; nt++)
#pragma unroll
            for (int j = 0; j < 4; j++) acc[mt][nt][j] = 0.f;

    auto comp = [&](int st) {
        uint32_t af[MT][4], bf[NT2][2];
#pragma unroll
        for (int mt = 0; mt < MT; mt++) {
            int r0 = wm * WTM + mt * 16 + g;
            af[mt][0] = As[st][r0    ][tig];
            af[mt][1] = As[st][r0 + 8][tig];
            af[mt][2] = As[st][r0    ][tig + 4];
            af[mt][3] = As[st][r0 + 8][tig + 4];
        }
#pragma unroll
        for (int nt = 0; nt < NT2; nt++) {
            int c0 = wn * WTN + nt * 8 + g;
            bf[nt][0] = Bs[st][c0][tig];
            bf[nt][1] = Bs[st][c0][tig + 4];
        }
#pragma unroll
        for (int mt = 0; mt < MT; mt++)
#pragma unroll
            for (int nt = 0; nt < NT2; nt++)
                mma16(acc[mt][nt], af[mt], bf[nt]);
    };

    loadG(0); storeS(0); __syncthreads();
    int cur = 0;
    for (int it = 1; it <= NK; it++) {
        if (it < NK) loadG(it * 16);
        comp(cur);
        if (it < NK) storeS(cur ^ 1);
        __syncthreads();
        cur ^= 1;
    }

#pragma unroll
    for (int mt = 0; mt < MT; mt++) {
        int r0 = m0 + wm * WTM + mt * 16 + g;
#pragma unroll
        for (int nt = 0; nt < NT2; nt++) {
            int col = n0 + wn * WTN + nt * 8 + 2 * tig;
            float v0 = acc[mt][nt][0], v1 = acc[mt][nt][1];
            float v2 = acc[mt][nt][2], v3 = acc[mt][nt][3];
            float b0f = colBias[col], b1f = colBias[col + 1];
            v0 += b0f + resid[(long long)r0 * D_ + col];
            v1 += b1f + resid[(long long)r0 * D_ + col + 1];
            v2 += b0f + resid[(long long)(r0 + 8) * D_ + col];
            v3 += b1f + resid[(long long)(r0 + 8) * D_ + col + 1];
            *reinterpret_cast<float2*>(&C[(long long)r0 * D_ + col]) =
                make_float2(v0, v1);
            *reinterpret_cast<float2*>(&C[(long long)(r0 + 8) * D_ + col]) =
                make_float2(v2, v3);
        }
    }
}

// ---------------------------------------------------------------------------
// Fused KS / cvec on packed arrays (unchanged).
// ---------------------------------------------------------------------------
__global__ void ks_cvec_kernel(const float* __restrict__ rwb,
                               const float* __restrict__ rrb)
{
    const int gw = (blockIdx.x * blockDim.x + threadIdx.x) >> 5;
    const int lane = threadIdx.x & 31;
    if (gw >= B_ * N_ * S_) return;
    const int s = gw % S_;
    const int n = (gw / S_) % N_;
    const int b = gw / (S_ * N_);

    const long long khI = (long long)(b * S_ + s) * DW + n * 32 + lane;
    const long long rI  = (long long)s * DW + n * 32 + lane;

    float2 kv = upk(g_khw[khI]);
    float2 rv = upk(g_rp[rI]);
    g_khw[khI] = pk(kv.x + rv.x, kv.y + rv.y);

    const int hb = n * H_ + 2 * lane;
    float acc = rwb[hb] * kv.x + rwb[hb + 1] * kv.y
              + rrb[hb] * rv.x + rrb[hb + 1] * rv.y;
#pragma unroll
    for (int o = 16; o; o >>= 1) acc += __shfl_xor_sync(~0u, acc, o);
    if (lane == 0) g_cvec[(long long)(b * N_ + n) * S_ + s] = acc;
}

// ---------------------------------------------------------------------------
// Fused flash attention, bf16. FBQ=128 (4 warps x 32 rows, MT=2), FBK=64.
// V loaded packed-along-h and re-paired along s via byte_perm (same rounding
// point as before -> identical numerics, half the V global traffic).
// ---------------------------------------------------------------------------
constexpr int FBQ = 128;
constexpr int FBK = 64;
constexpr int QWS = 36;
constexpr int VWS = 72;
constexpr int FSMEM_WORDS = FBQ * QWS + FBQ * QWS + (FBK / 2) * VWS + FBK;
constexpr int FSMEM_BYTES = FSMEM_WORDS * 4;

__global__ void __launch_bounds__(128) flash_kernel(const int* __restrict__ mask)
{
    extern __shared__ uint32_t smw[];
    uint32_t* Qs   = smw;
    uint32_t* KP   = Qs + FBQ * QWS;
    uint32_t* Vs   = KP + FBQ * QWS;
    float*    sAdd = reinterpret_cast<float*>(Vs + (FBK / 2) * VWS);

    const int z = blockIdx.y;
    const int b = z >> 4, n = z & 15;
    const int q0 = blockIdx.x * FBQ;
    const int tid = threadIdx.x, lane = tid & 31, w = tid >> 5;
    const int g = lane >> 2, tig = lane & 3;
    const int wr = w * 32;

    const uint32_t* Qg = g_qhw + (long long)b * S_ * DW + n * 32;
    const uint32_t* Kg = g_khw + (long long)b * S_ * DW + n * 32;
    const uint32_t* Vg = g_vhw + (long long)b * S_ * DW + n * 32;
    const float*    cv = g_cvec + (long long)z * S_;
    const int*      mk = mask + b * S_;

#pragma unroll
    for (int i = 0; i < 8; i++) {
        int v = tid + i * 128;
        int row = v >> 3, c = v & 7;
        uint4 t = *reinterpret_cast<const uint4*>(
            Qg + (long long)(q0 + row) * DW + 4 * c);
        *reinterpret_cast<uint4*>(Qs + row * QWS + 4 * c) = t;
    }

    float Oa[2][8][4];
#pragma unroll
    for (int mt = 0; mt < 2; mt++)
#pragma unroll
        for (int i = 0; i < 8; i++)
#pragma unroll
            for (int j = 0; j < 4; j++) Oa[mt][i][j] = 0.f;
    float mr[2][2], lr[2][2];
#pragma unroll
    for (int mt = 0; mt < 2; mt++) {
        mr[mt][0] = mr[mt][1] = -3.0e38f;
        lr[mt][0] = lr[mt][1] = 0.f;
    }

    for (int kt = 0; kt < S_ / FBK; kt++) {
        __syncthreads();
        const int kb = kt * FBK;
#pragma unroll
        for (int i = 0; i < 4; i++) {
            int v = tid + i * 128;
            int row = v >> 3, c = v & 7;
            uint4 t = *reinterpret_cast<const uint4*>(
                Kg + (long long)(kb + row) * DW + 4 * c);
            *reinterpret_cast<uint4*>(KP + row * QWS + 4 * c) = t;
        }
        // V: rows (2sw, 2sw+1) packed along h -> re-pair along s via prmt.
#pragma unroll
        for (int i = 0; i < 2; i++) {
            int v = tid + i * 128;            // 32 sw-rows x 8 word-quads
            int sw = v >> 3, c = v & 7;
            uint4 t0 = *reinterpret_cast<const uint4*>(
                Vg + (long long)(kb + 2 * sw) * DW + 4 * c);
            uint4 t1 = *reinterpret_cast<const uint4*>(
                Vg + (long long)(kb + 2 * sw + 1) * DW + 4 * c);
            uint4 o0, o1;
            o0.x = __byte_perm(t0.x, t1.x, 0x5410);
            o0.y = __byte_perm(t0.x, t1.x, 0x7632);
            o0.z = __byte_perm(t0.y, t1.y, 0x5410);
            o0.w = __byte_perm(t0.y, t1.y, 0x7632);
            o1.x = __byte_perm(t0.z, t1.z, 0x5410);
            o1.y = __byte_perm(t0.z, t1.z, 0x7632);
            o1.z = __byte_perm(t0.w, t1.w, 0x5410);
            o1.w = __byte_perm(t0.w, t1.w, 0x7632);
            *reinterpret_cast<uint4*>(Vs + sw * VWS + 8 * c)     = o0;
            *reinterpret_cast<uint4*>(Vs + sw * VWS + 8 * c + 4) = o1;
        }
        if (tid < FBK)
            sAdd[tid] = NORM_ * cv[kb + tid] - BIGC_ * (float)mk[kb + tid];
        __syncthreads();

        float Sa[2][8][4];
#pragma unroll
        for (int mt = 0; mt < 2; mt++)
#pragma unroll
            for (int i = 0; i < 8; i++)
#pragma unroll
                for (int j = 0; j < 4; j++) Sa[mt][i][j] = 0.f;
#pragma unroll
        for (int ks = 0; ks < 4; ks++) {
            uint32_t a[2][4];
#pragma unroll
            for (int mt = 0; mt < 2; mt++) {
                int rr = wr + mt * 16 + g;
                a[mt][0] = Qs[ rr      * QWS + ks * 8 + tig];
                a[mt][1] = Qs[(rr + 8) * QWS + ks * 8 + tig];
                a[mt][2] = Qs[ rr      * QWS + ks * 8 + tig + 4];
                a[mt][3] = Qs[(rr + 8) * QWS + ks * 8 + tig + 4];
            }
#pragma unroll
            for (int nt = 0; nt < 8; nt++) {
                uint32_t bfr[2];
                bfr[0] = KP[(nt * 8 + g) * QWS + ks * 8 + tig];
                bfr[1] = KP[(nt * 8 + g) * QWS + ks * 8 + tig + 4];
                mma16(Sa[0][nt], a[0], bfr);
                mma16(Sa[1][nt], a[1], bfr);
            }
        }
        __syncthreads();

#pragma unroll
        for (int mt = 0; mt < 2; mt++) {
            const int rr = wr + mt * 16 + g;
            float tm0 = -3.0e38f, tm1 = -3.0e38f;
#pragma unroll
            for (int nt = 0; nt < 8; nt++) {
                int c = nt * 8 + 2 * tig;
                float a0 = sAdd[c], a1 = sAdd[c + 1];
                Sa[mt][nt][0] = NORM_ * Sa[mt][nt][0] + a0;
                Sa[mt][nt][1] = NORM_ * Sa[mt][nt][1] + a1;
                Sa[mt][nt][2] = NORM_ * Sa[mt][nt][2] + a0;
                Sa[mt][nt][3] = NORM_ * Sa[mt][nt][3] + a1;
                tm0 = fmaxf(tm0, fmaxf(Sa[mt][nt][0], Sa[mt][nt][1]));
                tm1 = fmaxf(tm1, fmaxf(Sa[mt][nt][2], Sa[mt][nt][3]));
            }
            tm0 = fmaxf(tm0, __shfl_xor_sync(~0u, tm0, 1));
            tm0 = fmaxf(tm0, __shfl_xor_sync(~0u, tm0, 2));
            tm1 = fmaxf(tm1, __shfl_xor_sync(~0u, tm1, 1));
            tm1 = fmaxf(tm1, __shfl_xor_sync(~0u, tm1, 2));
            float mn0 = fmaxf(mr[mt][0], tm0), mn1 = fmaxf(mr[mt][1], tm1);
            float sc0 = __expf(mr[mt][0] - mn0), sc1 = __expf(mr[mt][1] - mn1);
            mr[mt][0] = mn0; mr[mt][1] = mn1;

            float rs0 = 0.f, rs1 = 0.f;
#pragma unroll
            for (int nt = 0; nt < 8; nt++) {
                float p0 = __expf(Sa[mt][nt][0] - mn0);
                float p1 = __expf(Sa[mt][nt][1] - mn0);
                float p2 = __expf(Sa[mt][nt][2] - mn1);
                float p3 = __expf(Sa[mt][nt][3] - mn1);
                rs0 += p0 + p1; rs1 += p2 + p3;
                KP[ rr      * QWS + nt * 4 + tig] = pk(p0, p1);
                KP[(rr + 8) * QWS + nt * 4 + tig] = pk(p2, p3);
            }
            rs0 += __shfl_xor_sync(~0u, rs0, 1);
            rs0 += __shfl_xor_sync(~0u, rs0, 2);
            rs1 += __shfl_xor_sync(~0u, rs1, 1);
            rs1 += __shfl_xor_sync(~0u, rs1, 2);
            lr[mt][0] = lr[mt][0] * sc0 + rs0;
            lr[mt][1] = lr[mt][1] * sc1 + rs1;
#pragma unroll
            for (int nt = 0; nt < 8; nt++) {
                Oa[mt][nt][0] *= sc0; Oa[mt][nt][1] *= sc0;
                Oa[mt][nt][2] *= sc1; Oa[mt][nt][3] *= sc1;
            }
        }
        __syncwarp();

#pragma unroll
        for (int ks = 0; ks < 4; ks++) {
            uint32_t a[2][4];
#pragma unroll
            for (int mt = 0; mt < 2; mt++) {
                int rr = wr + mt * 16 + g;
                a[mt][0] = KP[ rr      * QWS + ks * 8 + tig];
                a[mt][1] = KP[(rr + 8) * QWS + ks * 8 + tig];
                a[mt][2] = KP[ rr      * QWS + ks * 8 + tig + 4];
                a[mt][3] = KP[(rr + 8) * QWS + ks * 8 + tig + 4];
            }
#pragma unroll
            for (int nt = 0; nt < 8; nt++) {
                uint32_t bfr[2];
                bfr[0] = Vs[(ks * 8 + tig    ) * VWS + nt * 8 + g];
                bfr[1] = Vs[(ks * 8 + tig + 4) * VWS + nt * 8 + g];
                mma16(Oa[0][nt], a[0], bfr);
                mma16(Oa[1][nt], a[1], bfr);
            }
        }
    }

    uint32_t* Og = g_ow + (long long)b * S_ * DW + n * 32;
#pragma unroll
    for (int mt = 0; mt < 2; mt++) {
        const int rr = wr + mt * 16 + g;
        const float inv0 = 1.0f / lr[mt][0], inv1 = 1.0f / lr[mt][1];
#pragma unroll
        for (int nt = 0; nt < 8; nt++) {
            Og[(long long)(q0 + rr) * DW + nt * 4 + tig] =
                pk(Oa[mt][nt][0] * inv0, Oa[mt][nt][1] * inv0);
            Og[(long long)(q0 + rr + 8) * DW + nt * 4 + tig] =
                pk(Oa[mt][nt][2] * inv1, Oa[mt][nt][3] * inv1);
        }
    }
}

// ---------------------------------------------------------------------------
// LayerNorm in place on d_out rows (unchanged).
// ---------------------------------------------------------------------------
__global__ void __launch_bounds__(256)
ln_kernel(float* __restrict__ x, const float* __restrict__ gamma,
          const float* __restrict__ beta)
{
    float* p = x + (long long)blockIdx.x * D_;
    const int t = threadIdx.x;
    __shared__ float sred[8];

    float v[4];
    float s = 0.f;
#pragma unroll
    for (int i = 0; i < 4; i++) { v[i] = p[t + 256 * i]; s += v[i]; }
#pragma unroll
    for (int o = 16; o; o >>= 1) s += __shfl_xor_sync(~0u, s, o);
    if ((t & 31) == 0) sred[t >> 5] = s;
    __syncthreads();
    s = 0.f;
#pragma unroll
    for (int i = 0; i < 8; i++) s += sred[i];
    const float mean = s * (1.0f / D_);
    __syncthreads();

    float vs = 0.f;
#pragma unroll
    for (int i = 0; i < 4; i++) { float d = v[i] - mean; vs += d * d; }
#pragma unroll
    for (int o = 16; o; o >>= 1) vs += __shfl_xor_sync(~0u, vs, o);
    if ((t & 31) == 0) sred[t >> 5] = vs;
    __syncthreads();
    vs = 0.f;
#pragma unroll
    for (int i = 0; i < 8; i++) vs += sred[i];
    const float rstd = rsqrtf(vs * (1.0f / D_) + LNEPS_);

#pragma unroll
    for (int i = 0; i < 4; i++) {
        const int col = t + 256 * i;
        p[col] = (v[i] - mean) * rstd * gamma[col] + beta[col];
    }
}

// ---------------------------------------------------------------------------
// Host launcher
// ---------------------------------------------------------------------------
extern "C" void kernel_launch(void* const* d_in, const int* in_sizes, int n_in,
                              void* d_out, int out_size)
{
    const float* q        = (const float*)d_in[0];
    const float* k        = (const float*)d_in[1];
    const float* v        = (const float*)d_in[2];
    const float* pos_enc  = (const float*)d_in[3];
    const int*   mask     = (const int*)  d_in[4];
    const float* q_w      = (const float*)d_in[5];
    const float* k_w      = (const float*)d_in[6];
    const float* k_b      = (const float*)d_in[7];
    const float* v_w      = (const float*)d_in[8];
    const float* v_b      = (const float*)d_in[9];
    const float* rwb      = (const float*)d_in[10];
    const float* rrb      = (const float*)d_in[11];
    const float* r_kernel = (const float*)d_in[12];
    const float* post_w   = (const float*)d_in[13];
    const float* post_b   = (const float*)d_in[14];
    const float* ln_g     = (const float*)d_in[15];
    const float* ln_b     = (const float*)d_in[16];
    float* out = (float*)d_out;

    void* p;
    cudaGetSymbolAddress(&p, g_qhw); uint32_t* qhw = (uint32_t*)p;
    cudaGetSymbolAddress(&p, g_khw); uint32_t* khw = (uint32_t*)p;
    cudaGetSymbolAddress(&p, g_vhw); uint32_t* vhw = (uint32_t*)p;
    cudaGetSymbolAddress(&p, g_rp);  uint32_t* rp  = (uint32_t*)p;
    cudaGetSymbolAddress(&p, g_rw);  float*    rw  = (float*)p;
    cudaGetSymbolAddress(&p, g_ow);  uint32_t* ow  = (uint32_t*)p;

    // 0. r_kernel transpose [N,D,H] -> [D, N*H]
    rk_transpose<<<64, 256>>>(r_kernel);

    // 1. Merged projections: z = {q, k, v, r(pos_enc)} in one launch
    {
        GemmBatch4 bs;
        bs.b[0] = { q,       q_w, nullptr, qhw, B_ * S_ };
        bs.b[1] = { k,       k_w, k_b,     khw, B_ * S_ };
        bs.b[2] = { v,       v_w, v_b,     vhw, B_ * S_ };
        bs.b[3] = { pos_enc, rw,  nullptr, rp,  S_      };
        dim3 grid(D_ / 128, (B_ * S_) / 128, 4);
        tgemm_multi<128, 128, 2, 4><<<grid, 256>>>(bs, D_, D_, D_);
    }

    // 2. KS = kh + r (packed); cvec
    ks_cvec_kernel<<<(B_ * N_ * S_) / 8, 256>>>(rwb, rrb);

    // 3. Fused flash attention (scores + softmax + P@V) -> g_ow
    {
        cudaFuncSetAttribute(flash_kernel,
                             cudaFuncAttributeMaxDynamicSharedMemorySize,
                             FSMEM_BYTES);
        dim3 grid(S_ / FBQ, B_ * N_);
        flash_kernel<<<grid, 128, FSMEM_BYTES>>>(mask);
    }

    // 4. post GEMM + bias + residual -> d_out
    {
        dim3 grid(D_ / 128, (B_ * S_) / 128, 1);
        tgemm_post<128, 128, 2, 4><<<grid, 256>>>(
            ow, post_w, out, D_, D_, post_b, q);
    }

    // 5. LayerNorm in place
    ln_kernel<<<B_ * S_, 256>>>(out, ln_g, ln_b);
}